// round 15
// baseline (speedup 1.0000x reference)
#include <cuda_runtime.h>
#include <math_constants.h>

// Cumulative max along H for x[B=32, C=1, H=1024, W=2048] fp32.
// Single streaming pass: 256 MB read + 256 MB write (the traffic floor).
//
// R14 = R5 (measured optimum: float2 columns, 32768 threads, 1024x32
// grid -> 6.9 warps/SM, rolling ring-buffer pipeline U=32, ld.cs loads)
// with ONE change: stores use the DEFAULT cache policy instead of st.cs.
// st.cs (evict-first) forces immediate per-line writeback, so the
// L2->DRAM write stream interleaves with reads at fine grain (max bus
// turnaround). Default stores let dirty lines pool in the 126 MB L2 and
// drain in longer same-direction bursts via L2's writeback scheduler.
// Traffic unchanged; purely a DRAM-scheduling experiment.
//
// Design-sweep record (DRAM% / kernel us):
//   width:  float4 66.9 < float2 78.6 > float1 76.5
//   depth:  chunk-16 68.4 < roll-32 78.6 > roll-44 73.7 (reg blowup)
//   pairing: neutral;  traffic: single pass is the floor.

static constexpr int B = 32;
static constexpr int H = 1024;
static constexpr int W = 2048;
static constexpr int W2 = W / 2;            // 1024 float2 per row
static constexpr int NCOLS = B * W2;        // 32768 threads
static constexpr int U = 32;                // pipeline depth (float2 loads)
static constexpr int NCHUNK = H / U;        // 32 chunks

__global__ void __launch_bounds__(32)
cummax_h_kernel(const float2* __restrict__ x, float2* __restrict__ out) {
    int c = blockIdx.x * blockDim.x + threadIdx.x;   // 0 .. NCOLS-1

    int b  = c >> 10;          // c / 1024
    int w2 = c & (W2 - 1);     // c % 1024

    const float2* __restrict__ p = x   + (size_t)b * H * W2 + w2;
    float2*       __restrict__ q = out + (size_t)b * H * W2 + w2;

    float2 m = make_float2(-CUDART_INF_F, -CUDART_INF_F);

    float2 buf[U];

    // Prologue: fill the pipeline with rows 0..U-1.
    #pragma unroll
    for (int i = 0; i < U; i++)
        buf[i] = __ldcs(p + (size_t)i * W2);

    // Steady state: consume row hCur+i while refilling with row hCur+i+U.
    // The refill load is independent of the fmax chain and issues first,
    // so U loads stay in flight continuously with no drain windows.
    for (int cc = 0; cc < NCHUNK - 1; cc++) {
        int hCur = cc * U;
        int hNxt = hCur + U;
        #pragma unroll
        for (int i = 0; i < U; i++) {
            float2 v = buf[i];
            buf[i] = __ldcs(p + (size_t)(hNxt + i) * W2);
            m.x = fmaxf(m.x, v.x);
            m.y = fmaxf(m.y, v.y);
            q[(size_t)(hCur + i) * W2] = m;   // default policy: pool in L2
        }
    }

    // Epilogue: drain the last chunk (rows H-U .. H-1).
    {
        int hCur = (NCHUNK - 1) * U;
        #pragma unroll
        for (int i = 0; i < U; i++) {
            m.x = fmaxf(m.x, buf[i].x);
            m.y = fmaxf(m.y, buf[i].y);
            q[(size_t)(hCur + i) * W2] = m;
        }
    }
}

extern "C" void kernel_launch(void* const* d_in, const int* in_sizes, int n_in,
                              void* d_out, int out_size) {
    const float2* x   = (const float2*)d_in[0];
    float2*       out = (float2*)d_out;

    // 1024 blocks x 32 threads = 32768 threads, one per float2 column.
    cummax_h_kernel<<<NCOLS / 32, 32>>>(x, out);
}

// round 16
// speedup vs baseline: 1.0453x; 1.0453x over previous
#include <cuda_runtime.h>
#include <math_constants.h>

// Cumulative max along H for x[B=32, C=1, H=1024, W=2048] fp32.
// Single streaming pass: 256 MB read + 256 MB write (the traffic floor).
//
// FINAL = R5, the measured optimum across the complete design sweep
// (DRAM% at the kernel level):
//   width:   float4 66.9 < float2 78.6 > float1 76.5
//   depth:   chunk-16 68.4 < roll-32 78.6/78.8 > roll-44 73.7 (reg blowup)
//   stores:  default-policy 72.2 < st.cs 78.6 (default write-allocates
//            through L1: L1 38.9->59.5%, store path throttles loads)
//   pairing: neutral. Traffic: single pass is the floor; any H-split
//            or lookback scheme adds >=128 MB and is strictly worse.
//
// float2 column per thread (32768 threads, 1024 blocks x 32 -> 6.9
// warps/SM, <=1.2% SM imbalance), rolling ring-buffer pipeline U=32:
// each step refills buf[i] with the row U ahead BEFORE consuming, so
// 256 B/thread (~8 MB chip-wide) stays continuously in flight with no
// drain windows. ld.cs/st.cs keep the zero-reuse stream out of L1/L2.
// ~6.2 TB/s on a fully interleaved 50/50 R/W stream == practical HBM3e
// ceiling; L2 (38%), LSU, and issue (5.5%) all retain headroom.

static constexpr int B = 32;
static constexpr int H = 1024;
static constexpr int W = 2048;
static constexpr int W2 = W / 2;            // 1024 float2 per row
static constexpr int NCOLS = B * W2;        // 32768 threads
static constexpr int U = 32;                // pipeline depth (float2 loads)
static constexpr int NCHUNK = H / U;        // 32 chunks

__global__ void __launch_bounds__(32)
cummax_h_kernel(const float2* __restrict__ x, float2* __restrict__ out) {
    int c = blockIdx.x * blockDim.x + threadIdx.x;   // 0 .. NCOLS-1

    int b  = c >> 10;          // c / 1024
    int w2 = c & (W2 - 1);     // c % 1024

    const float2* __restrict__ p = x   + (size_t)b * H * W2 + w2;
    float2*       __restrict__ q = out + (size_t)b * H * W2 + w2;

    float2 m = make_float2(-CUDART_INF_F, -CUDART_INF_F);

    float2 buf[U];

    // Prologue: fill the pipeline with rows 0..U-1.
    #pragma unroll
    for (int i = 0; i < U; i++)
        buf[i] = __ldcs(p + (size_t)i * W2);

    // Steady state: consume row hCur+i while refilling with row hCur+i+U.
    // The refill load is independent of the fmax chain and issues first,
    // so U loads stay in flight continuously with no drain windows.
    for (int cc = 0; cc < NCHUNK - 1; cc++) {
        int hCur = cc * U;
        int hNxt = hCur + U;
        #pragma unroll
        for (int i = 0; i < U; i++) {
            float2 v = buf[i];
            buf[i] = __ldcs(p + (size_t)(hNxt + i) * W2);
            m.x = fmaxf(m.x, v.x);
            m.y = fmaxf(m.y, v.y);
            __stcs(q + (size_t)(hCur + i) * W2, m);
        }
    }

    // Epilogue: drain the last chunk (rows H-U .. H-1).
    {
        int hCur = (NCHUNK - 1) * U;
        #pragma unroll
        for (int i = 0; i < U; i++) {
            m.x = fmaxf(m.x, buf[i].x);
            m.y = fmaxf(m.y, buf[i].y);
            __stcs(q + (size_t)(hCur + i) * W2, m);
        }
    }
}

extern "C" void kernel_launch(void* const* d_in, const int* in_sizes, int n_in,
                              void* d_out, int out_size) {
    const float2* x   = (const float2*)d_in[0];
    float2*       out = (float2*)d_out;

    // 1024 blocks x 32 threads = 32768 threads, one per float2 column.
    cummax_h_kernel<<<NCOLS / 32, 32>>>(x, out);
}